// round 3
// baseline (speedup 1.0000x reference)
#include <cuda_runtime.h>

typedef unsigned long long ull;

// ---------------------------------------------------------------------------
// B=64, Cin=64, T=300, V=25, K=3, Cout=64
//   x:    [64][64][300][25]  addr = b*480000 + ci*7500 + t*25 + v
//   W:    [192][64]          o = k*64 + c
//   bias: [192]
//   A:    [3][25][25]
//   out:  [64][64][300][25]
//
// Fused kernel: one block = 8 pixels (b,t). SMEM holds x tile + full conv
// tile xc[3][64][8][26] + packed A. No global intermediate.
// f32x2 everywhere; stage-2 packs the v-reduction into lo/hi halves.
// ---------------------------------------------------------------------------

#define NBLK 2400                       // 19200 pixels / 8
__device__ float g_bsum[64 * NBLK];     // per-(c, block) partial sums
__device__ float g_bsq [64 * NBLK];
__device__ float g_scale[64];
__device__ float g_shift[64];

__device__ __forceinline__ ull pk(float lo, float hi) {
    ull r; asm("mov.b64 %0, {%1,%2};" : "=l"(r) : "f"(lo), "f"(hi)); return r;
}
__device__ __forceinline__ void upk(ull v, float& lo, float& hi) {
    asm("mov.b64 {%0,%1}, %2;" : "=f"(lo), "=f"(hi) : "l"(v));
}
__device__ __forceinline__ ull ffma2(ull a, ull b, ull c) {
    ull d; asm("fma.rn.f32x2 %0, %1, %2, %3;" : "=l"(d) : "l"(a), "l"(b), "l"(c)); return d;
}

// SMEM layout (bytes):
//   sXc: [3][64][8][26] f32  = 159744   (conv tile, v padded to 26)
//   sX : [64][8][26]   f32   =  53248   (input tile, v25 zeroed)
//   pA : [3][13][26]   ull   =   8112   (A packed as (A[2vp][w], A[2vp+1][w]))
#define OFF_SXC 0
#define OFF_SX  159744
#define OFF_PA  212992
#define SMEM_BYTES 221104

__global__ __launch_bounds__(256, 1)
void k_fused(const float* __restrict__ x, const float* __restrict__ W,
             const float* __restrict__ bias, const float* __restrict__ A,
             float* __restrict__ out) {
    extern __shared__ __align__(16) char smem[];
    float* sXc = reinterpret_cast<float*>(smem + OFF_SXC);
    float* sX  = reinterpret_cast<float*>(smem + OFF_SX);
    ull*   pA  = reinterpret_cast<ull*>(smem + OFF_PA);

    const int tid  = threadIdx.x;
    const int pix0 = blockIdx.x * 8;

    // ---- load x tile: warp w owns pixel w; lanes = v ----
    {
        const int pw = tid >> 5, lane = tid & 31;
        const int pix = pix0 + pw;
        const int b = pix / 300, t = pix - b * 300;
        const float* xb = x + b * 480000 + t * 25 + lane;
        if (lane < 25) {
            #pragma unroll 4
            for (int ci = 0; ci < 64; ++ci)
                sX[(ci * 8 + pw) * 26 + lane] = __ldg(xb + ci * 7500);
        } else if (lane == 25) {
            #pragma unroll 4
            for (int ci = 0; ci < 64; ++ci)
                sX[(ci * 8 + pw) * 26 + 25] = 0.f;   // pad column MUST be finite
        }
    }
    // ---- build packed A: pA[k][vp][w] = (A[k][2vp][w], A[k][2vp+1][w]) ----
    for (int i = tid; i < 1014; i += 256) {
        const int k = i / 338, r = i - k * 338;
        const int vp = r / 26, w = r - vp * 26;
        const int v0 = 2 * vp;
        const float lo = (w < 25) ? __ldg(&A[(k * 25 + v0) * 25 + w]) : 0.f;
        const float hi = (w < 25 && v0 + 1 < 25) ? __ldg(&A[(k * 25 + v0 + 1) * 25 + w]) : 0.f;
        pA[i] = pk(lo, hi);
    }
    __syncthreads();

    // ---- stage 1: xc[k][c][p][v] = bias + sum_ci W[k,c,ci] * x[ci][p][v] ----
    // thread = (p: 8) x (vh: 2) x (cg: 16); tile = 4c x 7 v-pairs.
    {
        const int p  = tid & 7;
        const int vh = (tid >> 3) & 1;
        const int cg = tid >> 4;
        const int cb = cg * 4, vpb = vh * 7;
        const ull* sX64  = reinterpret_cast<const ull*>(sX);
        ull*       sXc64 = reinterpret_cast<ull*>(sXc);

        #pragma unroll 1
        for (int k = 0; k < 3; ++k) {
            ull acc[4][7];
            #pragma unroll
            for (int i = 0; i < 4; ++i) {
                const float bv = __ldg(&bias[k * 64 + cb + i]);
                const ull bp = pk(bv, bv);
                #pragma unroll
                for (int j = 0; j < 7; ++j) acc[i][j] = bp;
            }
            const float* Wk = W + (k * 64 + cb) * 64;
            #pragma unroll 2
            for (int ci = 0; ci < 64; ++ci) {
                ull xv[7];
                #pragma unroll
                for (int j = 0; j < 7; ++j)
                    xv[j] = sX64[(ci * 8 + p) * 13 + vpb + j];  // vh=1,j=6 reads
                                                                // past-row: initialized
                                                                // smem, discarded below
                #pragma unroll
                for (int i = 0; i < 4; ++i) {
                    const float wv = __ldg(Wk + i * 64 + ci);
                    const ull wp = pk(wv, wv);
                    #pragma unroll
                    for (int j = 0; j < 7; ++j)
                        acc[i][j] = ffma2(wp, xv[j], acc[i][j]);
                }
            }
            #pragma unroll
            for (int i = 0; i < 4; ++i) {
                ull* dst = sXc64 + ((k * 64 + cb + i) * 8 + p) * 13 + vpb;
                #pragma unroll
                for (int j = 0; j < 7; ++j)
                    if (vpb + j < 13) dst[j] = acc[i][j];
            }
        }
    }
    __syncthreads();

    // ---- stage 2: out[c][p][w] = sum_{k,vp} xcpair(c,p,vp) * Apair(k,vp,w) ----
    // lo half accumulates even v, hi half odd v; added at the end.
    // thread = (cs: 32) x (p: 8); owns c = cs and cs+32, all 25 w.
    {
        const int cs = tid >> 3, p = tid & 7;
        const ull* sXc64 = reinterpret_cast<const ull*>(sXc);
        ull a0[26], a1[26];
        #pragma unroll
        for (int w = 0; w < 26; ++w) { a0[w] = 0ULL; a1[w] = 0ULL; }

        #pragma unroll 1
        for (int k = 0; k < 3; ++k) {
            #pragma unroll
            for (int vp = 0; vp < 13; ++vp) {
                const ull xq0 = sXc64[((k * 64 + cs)      * 8 + p) * 13 + vp];
                const ull xq1 = sXc64[((k * 64 + cs + 32) * 8 + p) * 13 + vp];
                const ulonglong2* pv =
                    reinterpret_cast<const ulonglong2*>(pA + (k * 13 + vp) * 26);
                #pragma unroll
                for (int wq = 0; wq < 13; ++wq) {
                    const ulonglong2 aa = pv[wq];
                    a0[2 * wq]     = ffma2(xq0, aa.x, a0[2 * wq]);
                    a0[2 * wq + 1] = ffma2(xq0, aa.y, a0[2 * wq + 1]);
                    a1[2 * wq]     = ffma2(xq1, aa.x, a1[2 * wq]);
                    a1[2 * wq + 1] = ffma2(xq1, aa.y, a1[2 * wq + 1]);
                }
            }
        }

        const int pix = pix0 + p;
        const int b = pix / 300, t = pix - b * 300;
        float* ob = out + b * 480000 + t * 25;
        float s0 = 0.f, q0 = 0.f, s1 = 0.f, q1 = 0.f;
        #pragma unroll
        for (int w = 0; w < 25; ++w) {
            float lo, hi; upk(a0[w], lo, hi);
            const float v = lo + hi;
            s0 += v; q0 += v * v;
            ob[cs * 7500 + w] = v;
        }
        #pragma unroll
        for (int w = 0; w < 25; ++w) {
            float lo, hi; upk(a1[w], lo, hi);
            const float v = lo + hi;
            s1 += v; q1 += v * v;
            ob[(cs + 32) * 7500 + w] = v;
        }

        // reduce over the 8 pixel lanes sharing this c (consecutive tids)
        #pragma unroll
        for (int off = 4; off > 0; off >>= 1) {
            s0 += __shfl_down_sync(0xffffffffu, s0, off, 8);
            q0 += __shfl_down_sync(0xffffffffu, q0, off, 8);
            s1 += __shfl_down_sync(0xffffffffu, s1, off, 8);
            q1 += __shfl_down_sync(0xffffffffu, q1, off, 8);
        }
        if (p == 0) {
            g_bsum[cs * NBLK + blockIdx.x]        = s0;
            g_bsq [cs * NBLK + blockIdx.x]        = q0;
            g_bsum[(cs + 32) * NBLK + blockIdx.x] = s1;
            g_bsq [(cs + 32) * NBLK + blockIdx.x] = q1;
        }
    }
}

// ---------------------------------------------------------------------------
// Reduce 2400 partials per channel (double), fold gamma/beta. grid 64.
// ---------------------------------------------------------------------------
__global__ __launch_bounds__(256) void k_stats2(const float* __restrict__ gamma,
                                                const float* __restrict__ beta) {
    const int c = blockIdx.x;
    __shared__ double ds[256], dq[256];
    double s = 0.0, q = 0.0;
    for (int j = threadIdx.x; j < NBLK; j += 256) {
        s += (double)g_bsum[c * NBLK + j];
        q += (double)g_bsq [c * NBLK + j];
    }
    ds[threadIdx.x] = s; dq[threadIdx.x] = q;
    __syncthreads();
    #pragma unroll
    for (int off = 128; off > 0; off >>= 1) {
        if (threadIdx.x < off) {
            ds[threadIdx.x] += ds[threadIdx.x + off];
            dq[threadIdx.x] += dq[threadIdx.x + off];
        }
        __syncthreads();
    }
    if (threadIdx.x == 0) {
        const double mean = ds[0] / 480000.0;
        const double var  = dq[0] / 480000.0 - mean * mean;
        const double rstd = 1.0 / sqrt(var + 1e-5);
        const float sc = (float)((double)gamma[c] * rstd);
        g_scale[c] = sc;
        g_shift[c] = beta[c] - (float)mean * sc;
    }
}

// ---------------------------------------------------------------------------
// In-place normalize. 7,680,000 float4.
// ---------------------------------------------------------------------------
__global__ __launch_bounds__(256) void k_bn(float* __restrict__ out) {
    const int i = blockIdx.x * 256 + threadIdx.x;
    if (i >= 7680000) return;
    const int c = (i / 1875) & 63;
    const float sc = g_scale[c];
    const float sh = g_shift[c];
    float4 v = reinterpret_cast<float4*>(out)[i];
    v.x = fmaf(v.x, sc, sh);
    v.y = fmaf(v.y, sc, sh);
    v.z = fmaf(v.z, sc, sh);
    v.w = fmaf(v.w, sc, sh);
    reinterpret_cast<float4*>(out)[i] = v;
}

// ---------------------------------------------------------------------------
extern "C" void kernel_launch(void* const* d_in, const int* in_sizes, int n_in,
                              void* d_out, int out_size) {
    const float* x     = (const float*)d_in[0];
    const float* W     = (const float*)d_in[1];
    const float* bias  = (const float*)d_in[2];
    const float* A     = (const float*)d_in[3];
    const float* gamma = (const float*)d_in[4];
    const float* beta  = (const float*)d_in[5];
    float* out = (float*)d_out;

    cudaFuncSetAttribute(k_fused, cudaFuncAttributeMaxDynamicSharedMemorySize,
                         SMEM_BYTES);
    k_fused <<<NBLK, 256, SMEM_BYTES>>>(x, W, bias, A, out);
    k_stats2<<<64, 256>>>(gamma, beta);
    k_bn    <<<30000, 256>>>(out);
}

// round 6
// speedup vs baseline: 1.1379x; 1.1379x over previous
#include <cuda_runtime.h>

typedef unsigned long long ull;

// ---------------------------------------------------------------------------
// B=64, Cin=64, T=300, V=25, K=3, Cout=64
//   x:    [64][64][300][25]  addr = b*480000 + ci*7500 + q, q = t*25+v
//   W:    [192][64]          o = k*64 + c
//   A:    [3][25][25]
//   out:  [64][64][300][25]
// xc scratch: [b][o][q] -> b*1440000 + o*7500 + q   (369 MB)
// ---------------------------------------------------------------------------

#define NBLK2 4800                       // graph tiles (1228800 rows / 256)
__device__ float g_xc[92160000];
__device__ float g_bsum[2 * NBLK2];
__device__ float g_bsq [2 * NBLK2];
__device__ int   g_btag[2 * NBLK2];
__device__ float g_scale[64];
__device__ float g_shift[64];

__device__ __forceinline__ ull pk(float lo, float hi) {
    ull r; asm("mov.b64 %0, {%1,%2};" : "=l"(r) : "f"(lo), "f"(hi)); return r;
}
__device__ __forceinline__ void upk(ull v, float& lo, float& hi) {
    asm("mov.b64 {%0,%1}, %2;" : "=f"(lo), "=f"(hi) : "l"(v));
}
__device__ __forceinline__ ull ffma2(ull a, ull b, ull c) {
    ull d; asm("fma.rn.f32x2 %0, %1, %2, %3;" : "=l"(d) : "l"(a), "l"(b), "l"(c)); return d;
}

// ---------------------------------------------------------------------------
// k_conv: 192 o x 128 p tile, K=64 resident. 384 threads, thread tile 8o x 8p.
// X read from DRAM exactly once. smem: sX[64][128] + sW[64][193] (padded).
// Store split into 4-pixel float4 groups: 7500 % 4 == 0 -> never straddles b.
// ---------------------------------------------------------------------------
#define CONV_SMEM (64*128*4 + 64*193*4)   // 82176 B

__global__ __launch_bounds__(384, 1)
void k_conv(const float* __restrict__ x, const float* __restrict__ W,
            const float* __restrict__ bias) {
    extern __shared__ __align__(16) float smem[];
    float* sX = smem;               // [ci][pl]   (64 x 128)
    float* sW = smem + 8192;        // [ci][o]    (64 x 193 pad: conflict-free)

    const int tid = threadIdx.x;
    const int p0  = blockIdx.x * 128;

    // load X tile (coalesced; each thread owns one pl, b computed per-pixel)
    {
        const int pl = tid & 127;
        const int cb = tid >> 7;                // 0..2
        const int p  = p0 + pl;
        const int b  = p / 7500;
        const int q  = p - b * 7500;
        const float* xb = x + b * 480000 + q;
        for (int ci = cb; ci < 64; ci += 3)
            sX[ci * 128 + pl] = __ldg(xb + ci * 7500);
    }
    // load W transposed: sW[ci][o]. coalesced LDG, conflict-free STS (pad 193)
    for (int i = tid; i < 12288; i += 384) {
        const int ci = i & 63;
        const int o  = i >> 6;
        sW[ci * 193 + o] = W[i];
    }
    __syncthreads();

    const int tx = tid & 15;        // p-group (8 p)
    const int ty = tid >> 4;        // o-group (8 o), 0..23
    const int oB = ty * 8;

    ull acc[8][4];
    #pragma unroll
    for (int i = 0; i < 8; ++i) {
        const float bv = __ldg(&bias[oB + i]);
        const ull bp = pk(bv, bv);
        #pragma unroll
        for (int j = 0; j < 4; ++j) acc[i][j] = bp;
    }

    const ull* sX64 = reinterpret_cast<const ull*>(sX);   // row stride 64 ull
    const float* wrow = sW + oB;

    #pragma unroll 8
    for (int ci = 0; ci < 64; ++ci) {
        ull xp[4];
        *reinterpret_cast<ulonglong2*>(&xp[0]) =
            *reinterpret_cast<const ulonglong2*>(&sX64[ci * 64 + tx * 4]);
        *reinterpret_cast<ulonglong2*>(&xp[2]) =
            *reinterpret_cast<const ulonglong2*>(&sX64[ci * 64 + tx * 4 + 2]);
        #pragma unroll
        for (int i = 0; i < 8; ++i) {
            const float wv = wrow[ci * 193 + i];
            const ull wp = pk(wv, wv);
            #pragma unroll
            for (int j = 0; j < 4; ++j)
                acc[i][j] = ffma2(wp, xp[j], acc[i][j]);
        }
    }

    // store: two independent 4-pixel float4 groups (each within one b).
    {
        const int pa = p0 + tx * 8;
        const int ba = pa / 7500, qa = pa - ba * 7500;
        const int pb = pa + 4;
        const int bb = pb / 7500, qb = pb - bb * 7500;
        float* dstA = g_xc + ba * 1440000 + qa;
        float* dstB = g_xc + bb * 1440000 + qb;
        #pragma unroll
        for (int i = 0; i < 8; ++i) {
            const int oo = (oB + i) * 7500;
            float4 f;
            upk(acc[i][0], f.x, f.y); upk(acc[i][1], f.z, f.w);
            *reinterpret_cast<float4*>(dstA + oo) = f;
            upk(acc[i][2], f.x, f.y); upk(acc[i][3], f.z, f.w);
            *reinterpret_cast<float4*>(dstB + oo) = f;
        }
    }
}

// ---------------------------------------------------------------------------
// k_graph: 256 rows x 32 w tile, K=75. 256 threads: (rg:64) x (wq:4).
// Thread tile: 2 row-ull (4 rows) x 8 w. In-warp 4x dedup on X loads.
// Fused per-tile BN partial stats (<=2 channel segments per tile).
// smem floats: sXc 75*258 -> pad to 19352 so sA is 16B-aligned; sA 75*32; red 4*264.
// ---------------------------------------------------------------------------
#define SXC_FLOATS 19352                 // 75*258 = 19350, +2 pad for 16B align
#define GRAPH_SMEM ((SXC_FLOATS + 75*32 + 4*264) * 4)   // 91232 B

__global__ __launch_bounds__(256, 2)
void k_graph(const float* __restrict__ A, float* __restrict__ out) {
    extern __shared__ __align__(16) float smem[];
    float* sXc = smem;                       // [kv][rl] pad 258
    float* sA  = smem + SXC_FLOATS;          // [kv][32] zero-padded w, 16B-aligned
    float* red = sA + 75 * 32;               // reduction scratch

    const int tid = threadIdx.x;
    const int r0  = blockIdx.x * 256;        // global row
    const int b   = r0 / 19200;              // 19200 % 256 == 0: no b straddle
    const int lr  = r0 - b * 19200;

    for (int i = tid; i < 2400; i += 256) {
        const int w = i & 31, kv = i >> 5;
        sA[i] = (w < 25) ? __ldg(&A[kv * 25 + w]) : 0.f;
    }
    #pragma unroll
    for (int k = 0; k < 3; ++k) {
        const float* src = g_xc + b * 1440000 + k * 480000 + lr * 25;
        for (int i = tid; i < 6400; i += 256) {
            const int rl = i / 25, v = i - rl * 25;
            sXc[(k * 25 + v) * 258 + rl] = src[i];
        }
    }
    __syncthreads();

    const int wq = tid & 3;                  // w-group of 8
    const int rg = tid >> 2;                 // row-group of 4 (2 ull)

    ull acc[2][8];
    #pragma unroll
    for (int u = 0; u < 2; ++u)
        #pragma unroll
        for (int w = 0; w < 8; ++w) acc[u][w] = 0ULL;

    const ull* sXc64 = reinterpret_cast<const ull*>(sXc);   // row stride 129 ull

    #pragma unroll 5
    for (int kv = 0; kv < 75; ++kv) {
        const ull x0 = sXc64[kv * 129 + rg * 2];
        const ull x1 = sXc64[kv * 129 + rg * 2 + 1];
        const float4 a0 = *reinterpret_cast<const float4*>(&sA[kv * 32 + wq * 8]);
        const float4 a1 = *reinterpret_cast<const float4*>(&sA[kv * 32 + wq * 8 + 4]);
        const float av[8] = {a0.x, a0.y, a0.z, a0.w, a1.x, a1.y, a1.z, a1.w};
        #pragma unroll
        for (int w = 0; w < 8; ++w) {
            const ull ap = pk(av[w], av[w]);
            acc[0][w] = ffma2(x0, ap, acc[0][w]);
            acc[1][w] = ffma2(x1, ap, acc[1][w]);
        }
    }
    __syncthreads();                         // done with sXc; reuse as sOut

    float* sOut = sXc;                       // [256][25] packed
    #pragma unroll
    for (int u = 0; u < 2; ++u) {
        const int r = rg * 4 + 2 * u;
        #pragma unroll
        for (int w = 0; w < 8; ++w) {
            const int wg = wq * 8 + w;
            if (wg < 25) {
                float lo, hi; upk(acc[u][w], lo, hi);
                sOut[r * 25 + wg]       = lo;
                sOut[(r + 1) * 25 + wg] = hi;
            }
        }
    }
    __syncthreads();

    // segmented BN partials: channel boundary at local row ib (<=1 per tile)
    const int rm = r0 % 300;
    const int ib = (300 - rm) % 300;         // 0..299; >=256 -> single segment
    const int split = (ib < 256) ? ib * 25 : 6400;
    float s0 = 0.f, q0 = 0.f, s1 = 0.f, q1 = 0.f;
    for (int i = tid; i < 6400; i += 256) {
        const float v = sOut[i];
        if (i < split) { s0 += v; q0 += v * v; }
        else           { s1 += v; q1 += v * v; }
    }
    red[tid] = s0; red[264 + tid] = q0; red[528 + tid] = s1; red[792 + tid] = q1;
    __syncthreads();
    #pragma unroll
    for (int off = 128; off > 0; off >>= 1) {
        if (tid < off) {
            red[tid]       += red[tid + off];
            red[264 + tid] += red[264 + tid + off];
            red[528 + tid] += red[528 + tid + off];
            red[792 + tid] += red[792 + tid + off];
        }
        __syncthreads();
    }
    if (tid == 0) {
        const int c0 = (r0 / 300) & 63;
        g_bsum[blockIdx.x * 2] = red[0];
        g_bsq [blockIdx.x * 2] = red[264];
        g_btag[blockIdx.x * 2] = c0;
        const int has2 = (ib < 256);
        g_bsum[blockIdx.x * 2 + 1] = red[528];
        g_bsq [blockIdx.x * 2 + 1] = red[792];
        g_btag[blockIdx.x * 2 + 1] = has2 ? (((r0 + ib) / 300) & 63) : -1;
    }

    // coalesced output store
    const float4* s4 = reinterpret_cast<const float4*>(sOut);
    float4* d4 = reinterpret_cast<float4*>(out + r0 * 25);
    for (int i = tid; i < 1600; i += 256)
        d4[i] = s4[i];
}

// ---------------------------------------------------------------------------
// k_stats2: gather tagged partials per channel (double), fold gamma/beta.
// ---------------------------------------------------------------------------
__global__ __launch_bounds__(256) void k_stats2(const float* __restrict__ gamma,
                                                const float* __restrict__ beta) {
    const int c = blockIdx.x;
    __shared__ double ds[256], dq[256];
    double s = 0.0, q = 0.0;
    for (int j = threadIdx.x; j < 2 * NBLK2; j += 256) {
        if (g_btag[j] == c) { s += (double)g_bsum[j]; q += (double)g_bsq[j]; }
    }
    ds[threadIdx.x] = s; dq[threadIdx.x] = q;
    __syncthreads();
    #pragma unroll
    for (int off = 128; off > 0; off >>= 1) {
        if (threadIdx.x < off) {
            ds[threadIdx.x] += ds[threadIdx.x + off];
            dq[threadIdx.x] += dq[threadIdx.x + off];
        }
        __syncthreads();
    }
    if (threadIdx.x == 0) {
        const double mean = ds[0] / 480000.0;
        const double var  = dq[0] / 480000.0 - mean * mean;
        const double rstd = 1.0 / sqrt(var + 1e-5);
        const float sc = (float)((double)gamma[c] * rstd);
        g_scale[c] = sc;
        g_shift[c] = beta[c] - (float)mean * sc;
    }
}

// ---------------------------------------------------------------------------
// k_bn: in-place normalize, 7,680,000 float4.
// ---------------------------------------------------------------------------
__global__ __launch_bounds__(256) void k_bn(float* __restrict__ out) {
    const int i = blockIdx.x * 256 + threadIdx.x;
    if (i >= 7680000) return;
    const int c = (i / 1875) & 63;
    const float sc = g_scale[c];
    const float sh = g_shift[c];
    float4 v = reinterpret_cast<float4*>(out)[i];
    v.x = fmaf(v.x, sc, sh);
    v.y = fmaf(v.y, sc, sh);
    v.z = fmaf(v.z, sc, sh);
    v.w = fmaf(v.w, sc, sh);
    reinterpret_cast<float4*>(out)[i] = v;
}

// ---------------------------------------------------------------------------
extern "C" void kernel_launch(void* const* d_in, const int* in_sizes, int n_in,
                              void* d_out, int out_size) {
    const float* x     = (const float*)d_in[0];
    const float* W     = (const float*)d_in[1];
    const float* bias  = (const float*)d_in[2];
    const float* A     = (const float*)d_in[3];
    const float* gamma = (const float*)d_in[4];
    const float* beta  = (const float*)d_in[5];
    float* out = (float*)d_out;

    cudaFuncSetAttribute(k_conv,  cudaFuncAttributeMaxDynamicSharedMemorySize, CONV_SMEM);
    cudaFuncSetAttribute(k_graph, cudaFuncAttributeMaxDynamicSharedMemorySize, GRAPH_SMEM);

    k_conv  <<<3750, 384, CONV_SMEM>>>(x, W, bias);
    k_graph <<<NBLK2, 256, GRAPH_SMEM>>>(A, out);
    k_stats2<<<64, 256>>>(gamma, beta);
    k_bn    <<<30000, 256>>>(out);
}

// round 9
// speedup vs baseline: 1.3941x; 1.2252x over previous
#include <cuda_runtime.h>
#include <cuda_bf16.h>
#include <cstdint>

typedef unsigned long long ull;
typedef unsigned int uint;

// ---------------------------------------------------------------------------
// B=64, Cin=64, T=300, V=25, K=3, Cout=64
//   x:    [64][64][300][25]  addr = b*480000 + ci*7500 + q, q = t*25+v
//   W:    [192][64]          o = k*64 + c
//   A:    [3][25][25]
//   out:  [64][64][300][25]
// xc scratch: [b][o][q] -> b*1440000 + o*7500 + q   (369 MB)
//
// Conv on mma.sync m16n8k16 bf16 (sm_80 baseline PTX -> valid on compute_103):
// bf16 hi/lo split, D = XhWh + XhWl + XlWh, fp32 register accumulators.
// ---------------------------------------------------------------------------

#define NBLK2 4800
__device__ float g_xc[92160000];
__device__ float g_bsum[2 * NBLK2];
__device__ float g_bsq [2 * NBLK2];
__device__ int   g_btag[2 * NBLK2];
__device__ float g_scale[64];
__device__ float g_shift[64];
// Pre-split W as b32 bf16-pairs: [0,6144) = Wh, [6144,12288) = Wl; idx = o*32+jp
__device__ uint g_Wpk[12288];

__device__ __forceinline__ ull pk(float lo, float hi) {
    ull r; asm("mov.b64 %0, {%1,%2};" : "=l"(r) : "f"(lo), "f"(hi)); return r;
}
__device__ __forceinline__ void upk(ull v, float& lo, float& hi) {
    asm("mov.b64 {%0,%1}, %2;" : "=f"(lo), "=f"(hi) : "l"(v));
}
__device__ __forceinline__ ull ffma2(ull a, ull b, ull c) {
    ull d; asm("fma.rn.f32x2 %0, %1, %2, %3;" : "=l"(d) : "l"(a), "l"(b), "l"(c)); return d;
}

__device__ __forceinline__ void hmma(float* c, const uint* a, const uint* b) {
    asm volatile(
        "mma.sync.aligned.m16n8k16.row.col.f32.bf16.bf16.f32 "
        "{%0,%1,%2,%3}, {%4,%5,%6,%7}, {%8,%9}, {%0,%1,%2,%3};"
        : "+f"(c[0]), "+f"(c[1]), "+f"(c[2]), "+f"(c[3])
        : "r"(a[0]), "r"(a[1]), "r"(a[2]), "r"(a[3]), "r"(b[0]), "r"(b[1]));
}

// ---------------------------------------------------------------------------
// k_prepW: W fp32 -> (Wh, Wl) bf16 pairs packed as b32.
// ---------------------------------------------------------------------------
__global__ void k_prepW(const float* __restrict__ W) {
    const int i = blockIdx.x * 256 + threadIdx.x;
    if (i >= 6144) return;
    const int o = i >> 5, jp = i & 31;
    const float v0 = W[o * 64 + 2 * jp];
    const float v1 = W[o * 64 + 2 * jp + 1];
    __nv_bfloat16 h0 = __float2bfloat16(v0);
    __nv_bfloat16 h1 = __float2bfloat16(v1);
    __nv_bfloat16 l0 = __float2bfloat16(v0 - __bfloat162float(h0));
    __nv_bfloat16 l1 = __float2bfloat16(v1 - __bfloat162float(h1));
    __nv_bfloat162 hp(h0, h1), lp(l0, l1);
    g_Wpk[i]        = *reinterpret_cast<uint*>(&hp);
    g_Wpk[6144 + i] = *reinterpret_cast<uint*>(&lp);
}

// ---------------------------------------------------------------------------
// k_conv_mma: grid 3750, 512 threads (4 M-warps x 4 N-warps, warp tile 32x48).
// SMEM (bytes): bias[0,768) | sXh[768) 128x37 b32 | sXl | sWh 192x37 b32 | sWl
// Row stride 37 b32: odd mod 32 -> transpose STS conflict-free; fragment
// LDS bank = (5g+t) mod 32 -> at most 2-way on 3 lane pairs.
// ---------------------------------------------------------------------------
#define OFF_XH 768
#define OFF_XL 19712
#define OFF_WH 38656
#define OFF_WL 67072
#define CONV_SMEM 95488

extern __shared__ __align__(16) char smem_dyn[];

__global__ __launch_bounds__(512, 1)
void k_conv_mma(const float* __restrict__ x, const float* __restrict__ bias) {
    char* smem = smem_dyn;
    float* sB  = reinterpret_cast<float*>(smem);
    uint*  sXh = reinterpret_cast<uint*>(smem + OFF_XH);
    uint*  sXl = reinterpret_cast<uint*>(smem + OFF_XL);
    uint*  sWh = reinterpret_cast<uint*>(smem + OFF_WH);
    uint*  sWl = reinterpret_cast<uint*>(smem + OFF_WL);

    const int tid = threadIdx.x;
    const int p0  = blockIdx.x * 128;

    if (tid < 192) sB[tid] = __ldg(&bias[tid]);

    // phase 1: load x (coalesced), split hi/lo, store transposed [p][ci]
    {
        const int pl = tid & 127;
        const int gr = tid >> 7;              // 0..3
        const int p  = p0 + pl;
        const int b  = p / 7500;
        const int q  = p - b * 7500;
        const float* xb = x + b * 480000 + q;
        #pragma unroll
        for (int jp = 0; jp < 8; ++jp) {
            const int ci = gr * 16 + jp * 2;
            const float v0 = __ldg(xb + ci * 7500);
            const float v1 = __ldg(xb + (ci + 1) * 7500);
            __nv_bfloat16 h0 = __float2bfloat16(v0);
            __nv_bfloat16 h1 = __float2bfloat16(v1);
            __nv_bfloat16 l0 = __float2bfloat16(v0 - __bfloat162float(h0));
            __nv_bfloat16 l1 = __float2bfloat16(v1 - __bfloat162float(h1));
            __nv_bfloat162 hp(h0, h1), lp(l0, l1);
            sXh[pl * 37 + (ci >> 1)] = *reinterpret_cast<uint*>(&hp);
            sXl[pl * 37 + (ci >> 1)] = *reinterpret_cast<uint*>(&lp);
        }
    }
    // phase 2: copy pre-split W into smem (row stride 37 b32)
    for (int i = tid; i < 6144; i += 512) {
        const int o = i >> 5, jp = i & 31;
        sWh[o * 37 + jp] = g_Wpk[i];
        sWl[o * 37 + jp] = g_Wpk[6144 + i];
    }
    __syncthreads();

    // mainloop
    const int wid  = tid >> 5;
    const int lane = tid & 31;
    const int mw = wid & 3;            // M quarter: rows mw*32
    const int nw = wid >> 2;           // N quarter: cols nw*48
    const int g  = lane >> 2;          // groupID 0..7
    const int t  = lane & 3;           // thread-in-group

    float acc[2][6][4];
    #pragma unroll
    for (int nf = 0; nf < 6; ++nf) {
        const float b0 = sB[nw * 48 + nf * 8 + 2 * t];
        const float b1 = sB[nw * 48 + nf * 8 + 2 * t + 1];
        #pragma unroll
        for (int i = 0; i < 2; ++i) {
            acc[i][nf][0] = b0; acc[i][nf][1] = b1;
            acc[i][nf][2] = b0; acc[i][nf][3] = b1;
        }
    }

    #pragma unroll
    for (int ks = 0; ks < 4; ++ks) {
        const int ko = ks * 8 + t;
        uint ah[2][4], al[2][4], bh[6][2], bl[6][2];
        #pragma unroll
        for (int i = 0; i < 2; ++i) {
            const int r = (mw * 32 + i * 16 + g) * 37 + ko;
            ah[i][0] = sXh[r];           ah[i][1] = sXh[r + 8 * 37];
            ah[i][2] = sXh[r + 4];       ah[i][3] = sXh[r + 8 * 37 + 4];
            al[i][0] = sXl[r];           al[i][1] = sXl[r + 8 * 37];
            al[i][2] = sXl[r + 4];       al[i][3] = sXl[r + 8 * 37 + 4];
        }
        #pragma unroll
        for (int nf = 0; nf < 6; ++nf) {
            const int rb = (nw * 48 + nf * 8 + g) * 37 + ko;
            bh[nf][0] = sWh[rb];  bh[nf][1] = sWh[rb + 4];
            bl[nf][0] = sWl[rb];  bl[nf][1] = sWl[rb + 4];
        }
        #pragma unroll
        for (int i = 0; i < 2; ++i)
            #pragma unroll
            for (int nf = 0; nf < 6; ++nf) {
                hmma(acc[i][nf], ah[i], bh[nf]);   // Xh*Wh
                hmma(acc[i][nf], ah[i], bl[nf]);   // Xh*Wl
                hmma(acc[i][nf], al[i], bh[nf]);   // Xl*Wh
            }
    }

    // epilogue: direct STG (rows g / g+8; cols = o pairs)
    #pragma unroll
    for (int i = 0; i < 2; ++i) {
        const int p1 = p0 + mw * 32 + i * 16 + g;
        const int p2 = p1 + 8;
        const int b1i = p1 / 7500, q1 = p1 - b1i * 7500;
        const int b2i = p2 / 7500, q2 = p2 - b2i * 7500;
        float* d1 = g_xc + b1i * 1440000 + q1;
        float* d2 = g_xc + b2i * 1440000 + q2;
        #pragma unroll
        for (int nf = 0; nf < 6; ++nf) {
            const int o = nw * 48 + nf * 8 + 2 * t;
            d1[o * 7500]       = acc[i][nf][0];
            d1[(o + 1) * 7500] = acc[i][nf][1];
            d2[o * 7500]       = acc[i][nf][2];
            d2[(o + 1) * 7500] = acc[i][nf][3];
        }
    }
}

// ---------------------------------------------------------------------------
// k_graph (R6, passing): 256 rows x 32 w, K=75, fused BN stats.
// ---------------------------------------------------------------------------
#define SXC_FLOATS 19352
#define GRAPH_SMEM ((SXC_FLOATS + 75*32 + 4*264) * 4)

__global__ __launch_bounds__(256, 2)
void k_graph(const float* __restrict__ A, float* __restrict__ out) {
    float* smem = reinterpret_cast<float*>(smem_dyn);
    float* sXc = smem;
    float* sA  = smem + SXC_FLOATS;
    float* red = sA + 75 * 32;

    const int tid = threadIdx.x;
    const int r0  = blockIdx.x * 256;
    const int b   = r0 / 19200;
    const int lr  = r0 - b * 19200;

    for (int i = tid; i < 2400; i += 256) {
        const int w = i & 31, kv = i >> 5;
        sA[i] = (w < 25) ? __ldg(&A[kv * 25 + w]) : 0.f;
    }
    #pragma unroll
    for (int k = 0; k < 3; ++k) {
        const float* src = g_xc + b * 1440000 + k * 480000 + lr * 25;
        for (int i = tid; i < 6400; i += 256) {
            const int rl = i / 25, v = i - rl * 25;
            sXc[(k * 25 + v) * 258 + rl] = src[i];
        }
    }
    __syncthreads();

    const int wq = tid & 3;
    const int rg = tid >> 2;

    ull acc[2][8];
    #pragma unroll
    for (int u = 0; u < 2; ++u)
        #pragma unroll
        for (int w = 0; w < 8; ++w) acc[u][w] = 0ULL;

    const ull* sXc64 = reinterpret_cast<const ull*>(sXc);

    #pragma unroll 5
    for (int kv = 0; kv < 75; ++kv) {
        const ull x0 = sXc64[kv * 129 + rg * 2];
        const ull x1 = sXc64[kv * 129 + rg * 2 + 1];
        const float4 a0 = *reinterpret_cast<const float4*>(&sA[kv * 32 + wq * 8]);
        const float4 a1 = *reinterpret_cast<const float4*>(&sA[kv * 32 + wq * 8 + 4]);
        const float av[8] = {a0.x, a0.y, a0.z, a0.w, a1.x, a1.y, a1.z, a1.w};
        #pragma unroll
        for (int w = 0; w < 8; ++w) {
            const ull ap = pk(av[w], av[w]);
            acc[0][w] = ffma2(x0, ap, acc[0][w]);
            acc[1][w] = ffma2(x1, ap, acc[1][w]);
        }
    }
    __syncthreads();

    float* sOut = sXc;
    #pragma unroll
    for (int u = 0; u < 2; ++u) {
        const int r = rg * 4 + 2 * u;
        #pragma unroll
        for (int w = 0; w < 8; ++w) {
            const int wg = wq * 8 + w;
            if (wg < 25) {
                float lo, hi; upk(acc[u][w], lo, hi);
                sOut[r * 25 + wg]       = lo;
                sOut[(r + 1) * 25 + wg] = hi;
            }
        }
    }
    __syncthreads();

    const int rm = r0 % 300;
    const int ib = (300 - rm) % 300;
    const int split = (ib < 256) ? ib * 25 : 6400;
    float s0 = 0.f, q0 = 0.f, s1 = 0.f, q1 = 0.f;
    for (int i = tid; i < 6400; i += 256) {
        const float v = sOut[i];
        if (i < split) { s0 += v; q0 += v * v; }
        else           { s1 += v; q1 += v * v; }
    }
    red[tid] = s0; red[264 + tid] = q0; red[528 + tid] = s1; red[792 + tid] = q1;
    __syncthreads();
    #pragma unroll
    for (int off = 128; off > 0; off >>= 1) {
        if (tid < off) {
            red[tid]       += red[tid + off];
            red[264 + tid] += red[264 + tid + off];
            red[528 + tid] += red[528 + tid + off];
            red[792 + tid] += red[792 + tid + off];
        }
        __syncthreads();
    }
    if (tid == 0) {
        const int c0 = (r0 / 300) & 63;
        g_bsum[blockIdx.x * 2] = red[0];
        g_bsq [blockIdx.x * 2] = red[264];
        g_btag[blockIdx.x * 2] = c0;
        const int has2 = (ib < 256);
        g_bsum[blockIdx.x * 2 + 1] = red[528];
        g_bsq [blockIdx.x * 2 + 1] = red[792];
        g_btag[blockIdx.x * 2 + 1] = has2 ? (((r0 + ib) / 300) & 63) : -1;
    }

    const float4* s4 = reinterpret_cast<const float4*>(sOut);
    float4* d4 = reinterpret_cast<float4*>(out + r0 * 25);
    for (int i = tid; i < 1600; i += 256)
        d4[i] = s4[i];
}

// ---------------------------------------------------------------------------
__global__ __launch_bounds__(256) void k_stats2(const float* __restrict__ gamma,
                                                const float* __restrict__ beta) {
    const int c = blockIdx.x;
    __shared__ double ds[256], dq[256];
    double s = 0.0, q = 0.0;
    for (int j = threadIdx.x; j < 2 * NBLK2; j += 256) {
        if (g_btag[j] == c) { s += (double)g_bsum[j]; q += (double)g_bsq[j]; }
    }
    ds[threadIdx.x] = s; dq[threadIdx.x] = q;
    __syncthreads();
    #pragma unroll
    for (int off = 128; off > 0; off >>= 1) {
        if (threadIdx.x < off) {
            ds[threadIdx.x] += ds[threadIdx.x + off];
            dq[threadIdx.x] += dq[threadIdx.x + off];
        }
        __syncthreads();
    }
    if (threadIdx.x == 0) {
        const double mean = ds[0] / 480000.0;
        const double var  = dq[0] / 480000.0 - mean * mean;
        const double rstd = 1.0 / sqrt(var + 1e-5);
        const float sc = (float)((double)gamma[c] * rstd);
        g_scale[c] = sc;
        g_shift[c] = beta[c] - (float)mean * sc;
    }
}

__global__ __launch_bounds__(256) void k_bn(float* __restrict__ out) {
    const int i = blockIdx.x * 256 + threadIdx.x;
    if (i >= 7680000) return;
    const int c = (i / 1875) & 63;
    const float sc = g_scale[c];
    const float sh = g_shift[c];
    float4 v = reinterpret_cast<float4*>(out)[i];
    v.x = fmaf(v.x, sc, sh);
    v.y = fmaf(v.y, sc, sh);
    v.z = fmaf(v.z, sc, sh);
    v.w = fmaf(v.w, sc, sh);
    reinterpret_cast<float4*>(out)[i] = v;
}

// ---------------------------------------------------------------------------
extern "C" void kernel_launch(void* const* d_in, const int* in_sizes, int n_in,
                              void* d_out, int out_size) {
    const float* x     = (const float*)d_in[0];
    const float* W     = (const float*)d_in[1];
    const float* bias  = (const float*)d_in[2];
    const float* A     = (const float*)d_in[3];
    const float* gamma = (const float*)d_in[4];
    const float* beta  = (const float*)d_in[5];
    float* out = (float*)d_out;

    cudaFuncSetAttribute(k_conv_mma, cudaFuncAttributeMaxDynamicSharedMemorySize, CONV_SMEM);
    cudaFuncSetAttribute(k_graph,    cudaFuncAttributeMaxDynamicSharedMemorySize, GRAPH_SMEM);

    k_prepW   <<<24, 256>>>(W);
    k_conv_mma<<<3750, 512, CONV_SMEM>>>(x, bias);
    k_graph   <<<NBLK2, 256, GRAPH_SMEM>>>(A, out);
    k_stats2  <<<64, 256>>>(gamma, beta);
    k_bn      <<<30000, 256>>>(out);
}